// round 1
// baseline (speedup 1.0000x reference)
#include <cuda_runtime.h>
#include <math.h>

#define LDIM   1024
#define NROWS  32768   // B*D = 64*512
#define KCOEF  5

// Scratch (allocation-free per harness rules)
__device__ float g_w[LDIM];
__device__ float g_att[NROWS];
__device__ float g_stats[2];   // [0]=mean, [1]=inv_std

// ---------------------------------------------------------------------------
// Kernel 1: fold DCT low-freq rows into a single length-L weight vector.
// w[l] = sum_k fc_w[k] * C[k,l],  C = orthonormal DCT-II rows 0..K-1.
// ---------------------------------------------------------------------------
__global__ void compute_w_kernel(const float* __restrict__ fc_w) {
    int l = threadIdx.x;             // 1024 threads, 1 block
    const float sqrt2L = sqrtf(2.0f / (float)LDIM);
    const float pi = 3.14159265358979323846f;
    float acc = 0.0f;
#pragma unroll
    for (int k = 0; k < KCOEF; k++) {
        float c = cosf(pi * ((float)l + 0.5f) * (float)k / (float)LDIM) * sqrt2L;
        if (k == 0) c *= 0.70710678118654752f;   // row 0 scaled by 1/sqrt(2)
        acc += fc_w[k] * c;
    }
    g_w[l] = acc;
}

// ---------------------------------------------------------------------------
// Kernel 2 (the HBM-bound one): per-row dot product. One warp per 1024-float
// row; 8 float4 loads per lane (MLP=8), coalesced; warp shuffle reduction.
// ---------------------------------------------------------------------------
__global__ void __launch_bounds__(256) dot_kernel(const float4* __restrict__ x,
                                                  const float* __restrict__ fc_b) {
    __shared__ float sw[LDIM];
    int t = threadIdx.x;
    // stage w into shared once per block
    for (int i = t; i < LDIM; i += 256) sw[i] = g_w[i];
    __syncthreads();

    int warp = t >> 5;
    int lane = t & 31;
    int row  = blockIdx.x * 8 + warp;        // 4096 blocks * 8 warps = 32768 rows

    const float4* xr = x + (size_t)row * (LDIM / 4);
    const float4* wr = (const float4*)sw;

    float acc = 0.0f;
#pragma unroll
    for (int j = 0; j < 8; j++) {
        int idx = j * 32 + lane;
        float4 v = xr[idx];
        float4 w = wr[idx];
        acc += v.x * w.x + v.y * w.y + v.z * w.z + v.w * w.w;
    }
#pragma unroll
    for (int off = 16; off; off >>= 1)
        acc += __shfl_xor_sync(0xffffffffu, acc, off);

    if (lane == 0) g_att[row] = acc + fc_b[0];
}

// ---------------------------------------------------------------------------
// Kernel 3: deterministic single-block reduction for BatchNorm stats
// (biased variance, training-mode over all B*D values).
// ---------------------------------------------------------------------------
__global__ void stats_kernel() {
    __shared__ float ssum[1024];
    __shared__ float ssq[1024];
    int t = threadIdx.x;
    float s = 0.0f, q = 0.0f;
    for (int i = t; i < NROWS; i += 1024) {
        float v = g_att[i];
        s += v;
        q += v * v;
    }
    ssum[t] = s; ssq[t] = q;
    __syncthreads();
    for (int off = 512; off; off >>= 1) {
        if (t < off) { ssum[t] += ssum[t + off]; ssq[t] += ssq[t + off]; }
        __syncthreads();
    }
    if (t == 0) {
        float mean = ssum[0] / (float)NROWS;
        float var  = ssq[0] / (float)NROWS - mean * mean;
        g_stats[0] = mean;
        g_stats[1] = rsqrtf(var + 1e-5f);
    }
}

// ---------------------------------------------------------------------------
// Kernel 4: BN affine + exact (erf) GELU + sigmoid gate; write both outputs.
// ---------------------------------------------------------------------------
__global__ void epilogue_kernel(float* __restrict__ out,
                                const float* __restrict__ bn_gamma,
                                const float* __restrict__ bn_beta,
                                const float* __restrict__ conv_w,
                                const float* __restrict__ conv_b,
                                int out_size) {
    int i = blockIdx.x * blockDim.x + threadIdx.x;
    if (i >= NROWS) return;
    float mean = g_stats[0];
    float inv  = g_stats[1];
    float a = (g_att[i] - mean) * inv * bn_gamma[0] + bn_beta[0];
    // exact GELU (torch nn.GELU default, erf form)
    a = 0.5f * a * (1.0f + erff(a * 0.70710678118654752f));
    float z = a * conv_w[0] + conv_b[0];
    float g = 1.0f / (1.0f + expf(-z));
    out[i] = g;
    if (out_size >= 2 * NROWS) out[i + NROWS] = g;   // att2 == att1
}

// ---------------------------------------------------------------------------
// Inputs (metadata order): x[64,512,1024] f32, fc_w[5], fc_b[1],
//                          bn_gamma[1], bn_beta[1], conv_w[1], conv_b[1]
// Output: (att1, att2) each [64,512,1] -> 2*32768 f32
// ---------------------------------------------------------------------------
extern "C" void kernel_launch(void* const* d_in, const int* in_sizes, int n_in,
                              void* d_out, int out_size) {
    const float4* x       = (const float4*)d_in[0];
    const float*  fc_w    = (const float*)d_in[1];
    const float*  fc_b    = (const float*)d_in[2];
    const float*  bn_gamma = (const float*)d_in[3];
    const float*  bn_beta  = (const float*)d_in[4];
    const float*  conv_w  = (const float*)d_in[5];
    const float*  conv_b  = (const float*)d_in[6];
    float* out = (float*)d_out;

    compute_w_kernel<<<1, LDIM>>>(fc_w);
    dot_kernel<<<NROWS / 8, 256>>>(x, fc_b);
    stats_kernel<<<1, 1024>>>();
    epilogue_kernel<<<(NROWS + 255) / 256, 256>>>(out, bn_gamma, bn_beta,
                                                  conv_w, conv_b, out_size);
}

// round 2
// speedup vs baseline: 1.0577x; 1.0577x over previous
#include <cuda_runtime.h>
#include <math.h>

#define LDIM    1024
#define NROWS   32768      // B*D = 64*512
#define KCOEF   5
#define NBLK_A  4096       // NROWS / 8 rows-per-block
#define NBLK_B  128

// Scratch (allocation-free per harness rules)
__device__ float  g_att[NROWS];
__device__ float2 g_partial[NBLK_A];   // per-block {sum, sumsq}

// ---------------------------------------------------------------------------
// Kernel A: fused w-build + per-row dot + per-block stats partial.
// 4096 blocks x 256 threads; one warp per 1024-float row (8 rows/block).
// ---------------------------------------------------------------------------
__global__ void __launch_bounds__(256) dot_kernel(const float4* __restrict__ x,
                                                  const float* __restrict__ fc_w,
                                                  const float* __restrict__ fc_b) {
    __shared__ float sw[LDIM];
    __shared__ float s_att[8];
    int t = threadIdx.x;

    // Build folded DCT weight vector in shared (each thread: 4 elems, 5 cosf each).
    {
        const float sqrt2L = sqrtf(2.0f / (float)LDIM);
        const float pi = 3.14159265358979323846f;
        float w0 = fc_w[0], w1 = fc_w[1], w2 = fc_w[2], w3 = fc_w[3], w4 = fc_w[4];
#pragma unroll
        for (int j = 0; j < 4; j++) {
            int l = t + j * 256;
            float ph = pi * ((float)l + 0.5f) / (float)LDIM;
            float acc = w0 * sqrt2L * 0.70710678118654752f;
            acc += w1 * cosf(ph)          * sqrt2L;
            acc += w2 * cosf(2.0f * ph)   * sqrt2L;
            acc += w3 * cosf(3.0f * ph)   * sqrt2L;
            acc += w4 * cosf(4.0f * ph)   * sqrt2L;
            sw[l] = acc;
        }
    }
    __syncthreads();

    int warp = t >> 5;
    int lane = t & 31;
    int row  = blockIdx.x * 8 + warp;

    const float4* xr = x + (size_t)row * (LDIM / 4);
    const float4* wr = (const float4*)sw;

    float acc = 0.0f;
#pragma unroll
    for (int j = 0; j < 8; j++) {
        int idx = j * 32 + lane;
        float4 v = xr[idx];
        float4 w = wr[idx];
        acc += v.x * w.x + v.y * w.y + v.z * w.z + v.w * w.w;
    }
#pragma unroll
    for (int off = 16; off; off >>= 1)
        acc += __shfl_xor_sync(0xffffffffu, acc, off);

    float att = acc + fc_b[0];
    if (lane == 0) {
        g_att[row] = att;
        s_att[warp] = att;
    }
    __syncthreads();

    // Thread 0: deterministic per-block stats partial over the 8 row values.
    if (t == 0) {
        float s = 0.0f, q = 0.0f;
#pragma unroll
        for (int i = 0; i < 8; i++) {
            float v = s_att[i];
            s += v;
            q += v * v;
        }
        g_partial[blockIdx.x] = make_float2(s, q);
    }
}

// ---------------------------------------------------------------------------
// Kernel B: redundant-per-block stats reduction + BN + GELU + sigmoid gate.
// 128 blocks x 256 threads; each block handles 256 rows.
// ---------------------------------------------------------------------------
__global__ void __launch_bounds__(256) epilogue_kernel(float* __restrict__ out,
                                                       const float* __restrict__ bn_gamma,
                                                       const float* __restrict__ bn_beta,
                                                       const float* __restrict__ conv_w,
                                                       const float* __restrict__ conv_b,
                                                       int out_size) {
    __shared__ float ssum[256];
    __shared__ float ssq[256];
    int t = threadIdx.x;

    // Every block reduces all 4096 partials (32 KB; L2-resident, fixed order).
    float s = 0.0f, q = 0.0f;
#pragma unroll
    for (int j = 0; j < NBLK_A / 256; j++) {
        float2 p = g_partial[t + j * 256];
        s += p.x;
        q += p.y;
    }
    ssum[t] = s; ssq[t] = q;
    __syncthreads();
    for (int off = 128; off; off >>= 1) {
        if (t < off) { ssum[t] += ssum[t + off]; ssq[t] += ssq[t + off]; }
        __syncthreads();
    }
    float mean = ssum[0] / (float)NROWS;
    float var  = ssq[0] / (float)NROWS - mean * mean;
    float inv  = rsqrtf(var + 1e-5f);

    int i = blockIdx.x * 256 + t;
    float a = (g_att[i] - mean) * inv * bn_gamma[0] + bn_beta[0];
    // exact GELU (erf form, torch nn.GELU default)
    a = 0.5f * a * (1.0f + erff(a * 0.70710678118654752f));
    float z = a * conv_w[0] + conv_b[0];
    float g = 1.0f / (1.0f + expf(-z));
    out[i] = g;
    if (out_size >= 2 * NROWS) out[i + NROWS] = g;   // att2 == att1
}

// ---------------------------------------------------------------------------
// Inputs (metadata order): x[64,512,1024] f32, fc_w[5], fc_b[1],
//                          bn_gamma[1], bn_beta[1], conv_w[1], conv_b[1]
// Output: (att1, att2) each [B, D, 1] -> 2*32768 f32
// ---------------------------------------------------------------------------
extern "C" void kernel_launch(void* const* d_in, const int* in_sizes, int n_in,
                              void* d_out, int out_size) {
    const float4* x        = (const float4*)d_in[0];
    const float*  fc_w     = (const float*)d_in[1];
    const float*  fc_b     = (const float*)d_in[2];
    const float*  bn_gamma = (const float*)d_in[3];
    const float*  bn_beta  = (const float*)d_in[4];
    const float*  conv_w   = (const float*)d_in[5];
    const float*  conv_b   = (const float*)d_in[6];
    float* out = (float*)d_out;

    dot_kernel<<<NBLK_A, 256>>>(x, fc_w, fc_b);
    epilogue_kernel<<<NBLK_B, 256>>>(out, bn_gamma, bn_beta, conv_w, conv_b, out_size);
}

// round 3
// speedup vs baseline: 1.1489x; 1.0862x over previous
#include <cuda_runtime.h>
#include <math.h>

#define LDIM     1024
#define NROWS    32768          // B*D = 64*512
#define NBLK     256
#define TPB      512
#define RPB      128            // rows per block (16 warps * 8 rows)

// Scratch (allocation-free per harness rules)
__device__ float2   g_partial[NBLK];
__device__ unsigned g_ctr = 0;          // monotonic arrival counter (never reset)

__global__ void __launch_bounds__(TPB, 2)
fused_kernel(const float4* __restrict__ x,
             const float*  __restrict__ fc_w,
             const float*  __restrict__ fc_b,
             const float*  __restrict__ bn_gamma,
             const float*  __restrict__ bn_beta,
             const float*  __restrict__ conv_w,
             const float*  __restrict__ conv_b,
             float* __restrict__ out, int out_size) {
    __shared__ float sw[LDIM];
    __shared__ float s_att[RPB];
    __shared__ float s_mi[2];           // mean, inv_std

    const int t    = threadIdx.x;
    const int warp = t >> 5;
    const int lane = t & 31;
    const int bid  = blockIdx.x;

    // ---- build folded DCT weight vector: w[l] = sum_k fc_w[k]*C[k,l] ----
    {
        const float sqrt2L = sqrtf(2.0f / (float)LDIM);
        const float pi = 3.14159265358979323846f;
        float w0 = fc_w[0], w1 = fc_w[1], w2 = fc_w[2], w3 = fc_w[3], w4 = fc_w[4];
#pragma unroll
        for (int j = 0; j < LDIM / TPB; j++) {
            int l = t + j * TPB;
            float ph = pi * ((float)l + 0.5f) / (float)LDIM;
            float acc = w0 * sqrt2L * 0.70710678118654752f;
            acc += w1 * cosf(ph)        * sqrt2L;
            acc += w2 * cosf(2.0f * ph) * sqrt2L;
            acc += w3 * cosf(3.0f * ph) * sqrt2L;
            acc += w4 * cosf(4.0f * ph) * sqrt2L;
            sw[l] = acc;
        }
    }
    __syncthreads();

    // ---- phase 1: per-row dots (1 warp -> 8 rows), att kept in shared ----
    const float4* wr = (const float4*)sw;
    const float fcb = fc_b[0];
    int rowbase = bid * RPB + warp * 8;
#pragma unroll 1
    for (int r = 0; r < 8; r++) {
        const float4* xr = x + (size_t)(rowbase + r) * (LDIM / 4);
        float acc = 0.0f;
#pragma unroll
        for (int j = 0; j < 8; j++) {
            int idx = j * 32 + lane;
            float4 v = __ldcs(xr + idx);       // streaming: evict-first
            float4 w = wr[idx];
            acc += v.x * w.x + v.y * w.y + v.z * w.z + v.w * w.w;
        }
#pragma unroll
        for (int off = 16; off; off >>= 1)
            acc += __shfl_xor_sync(0xffffffffu, acc, off);
        if (lane == 0) s_att[warp * 8 + r] = acc + fcb;
    }
    __syncthreads();

    // ---- block stats partial (warp 0, fixed order) ----
    if (warp == 0) {
        float s = 0.0f, q = 0.0f;
#pragma unroll
        for (int j = 0; j < RPB / 32; j++) {
            float v = s_att[lane + 32 * j];
            s += v;
            q += v * v;
        }
#pragma unroll
        for (int off = 16; off; off >>= 1) {
            s += __shfl_xor_sync(0xffffffffu, s, off);
            q += __shfl_xor_sync(0xffffffffu, q, off);
        }
        if (lane == 0) g_partial[bid] = make_float2(s, q);
    }

    // ---- grid barrier (all 256 blocks resident; monotonic counter) ----
    __threadfence();                    // release: partial visible before arrive
    __syncthreads();                    // whole block's work done before arrive
    if (t == 0) {
        unsigned old = atomicAdd(&g_ctr, 1u);
        unsigned target = old - (old % NBLK) + NBLK;   // this generation's goal
        unsigned c;
        do {
            asm volatile("ld.acquire.gpu.u32 %0, [%1];" : "=r"(c) : "l"(&g_ctr));
        } while (c < target);
    }
    __syncthreads();

    // ---- global stats (warp 0 reduces 256 partials, L2-coherent reads) ----
    if (warp == 0) {
        float s = 0.0f, q = 0.0f;
#pragma unroll
        for (int j = 0; j < NBLK / 32; j++) {
            float2 p = __ldcg(&g_partial[lane + 32 * j]);
            s += p.x;
            q += p.y;
        }
#pragma unroll
        for (int off = 16; off; off >>= 1) {
            s += __shfl_xor_sync(0xffffffffu, s, off);
            q += __shfl_xor_sync(0xffffffffu, q, off);
        }
        if (lane == 0) {
            float mean = s / (float)NROWS;
            float var  = q / (float)NROWS - mean * mean;
            s_mi[0] = mean;
            s_mi[1] = rsqrtf(var + 1e-5f);
        }
    }
    __syncthreads();

    // ---- epilogue: BN + exact GELU + sigmoid; write both output halves ----
    if (t < RPB) {
        float a = (s_att[t] - s_mi[0]) * s_mi[1] * bn_gamma[0] + bn_beta[0];
        a = 0.5f * a * (1.0f + erff(a * 0.70710678118654752f));
        float z = a * conv_w[0] + conv_b[0];
        float g = 1.0f / (1.0f + expf(-z));
        int i = bid * RPB + t;
        out[i] = g;
        if (out_size >= 2 * NROWS) out[i + NROWS] = g;
    }
}

// ---------------------------------------------------------------------------
// Inputs (metadata order): x[64,512,1024] f32, fc_w[5], fc_b[1],
//                          bn_gamma[1], bn_beta[1], conv_w[1], conv_b[1]
// Output: (att1, att2) each [B, D, 1] -> 2*32768 f32
// ---------------------------------------------------------------------------
extern "C" void kernel_launch(void* const* d_in, const int* in_sizes, int n_in,
                              void* d_out, int out_size) {
    const float4* x        = (const float4*)d_in[0];
    const float*  fc_w     = (const float*)d_in[1];
    const float*  fc_b     = (const float*)d_in[2];
    const float*  bn_gamma = (const float*)d_in[3];
    const float*  bn_beta  = (const float*)d_in[4];
    const float*  conv_w   = (const float*)d_in[5];
    const float*  conv_b   = (const float*)d_in[6];
    float* out = (float*)d_out;

    fused_kernel<<<NBLK, TPB>>>(x, fc_w, fc_b, bn_gamma, bn_beta,
                                conv_w, conv_b, out, out_size);
}